// round 7
// baseline (speedup 1.0000x reference)
#include <cuda_runtime.h>
#include <stdint.h>
#include <math.h>

#define NN 16384
#define DC 128              // concatenated feature cols (= GEMM N)
#define BM 64               // M tile per CTA (2 CTAs/SM)
#define BK 32               // K tile (32 fp32 = 128 bytes/row)
#define KITERS (NN / BK)    // 512
#define TILEA (BM * 128)    // 8 KB
#define TILEBB (DC * 128)   // 16 KB
#define NSTAGE 4
#define STAGEB (TILEA + TILEBB)               // 24 KB
#define SMEM_BYTES (1024 + NSTAGE * STAGEB)   // ~97 KB -> 2 CTAs/SM

// ---------------- scratch (device globals; no allocation) ----------------
__device__ float g_Pt[(size_t)DC * NN];  // B^T: [c][k] n-major, tf32-rounded bits (8 MB)
__device__ float g_X [(size_t)NN * DC];  // layer activations, row-major fp32 (8 MB)

// ---------------- helpers ----------------
__device__ __forceinline__ uint32_t s2u(const void* p) {
    uint32_t a;
    asm("{ .reg .u64 t; cvta.to.shared.u64 t, %1; cvt.u32.u64 %0, t; }" : "=r"(a) : "l"(p));
    return a;
}
__device__ __forceinline__ float eluf(float x) { return x > 0.f ? x : expm1f(x); }
__device__ __forceinline__ uint32_t tf32r(float x) {
    uint32_t u; asm("cvt.rna.tf32.f32 %0, %1;" : "=r"(u) : "f"(x)); return u;
}
__device__ __forceinline__ void cpa16(uint32_t saddr, const void* gaddr) {
    asm volatile("cp.async.cg.shared.global [%0], [%1], 16;" :: "r"(saddr), "l"(gaddr));
}
__device__ __forceinline__ void ldsm4(uint32_t r[4], uint32_t addr) {
    asm volatile("ldmatrix.sync.aligned.m8n8.x4.shared.b16 {%0,%1,%2,%3}, [%4];"
                 : "=r"(r[0]), "=r"(r[1]), "=r"(r[2]), "=r"(r[3]) : "r"(addr));
}
__device__ __forceinline__ void mma_tf32(float d[4], const uint32_t a[4],
                                         uint32_t b0, uint32_t b1) {
    asm volatile("mma.sync.aligned.m16n8k8.row.col.f32.tf32.tf32.f32 "
                 "{%0,%1,%2,%3}, {%4,%5,%6,%7}, {%8,%9}, {%0,%1,%2,%3};"
                 : "+f"(d[0]), "+f"(d[1]), "+f"(d[2]), "+f"(d[3])
                 : "r"(a[0]), "r"(a[1]), "r"(a[2]), "r"(a[3]), "r"(b0), "r"(b1));
}

// Compensation for HMMA.TF32 truncation (RZ) of raw-fp32 A operand:
// E[rel err] = 2^-11 * ln2 = 3.385e-4 (adj ~ U(0,1) => mantissa uniform).
#define SCOMP 1.0003385f

// ---------------- prep: P^T[c][k] = tf32( (elu?)in @ blockdiag(W,W) )^T ----------------
__global__ __launch_bounds__(256) void prep_kernel(const float* __restrict__ in,
                                                   const float* __restrict__ W,
                                                   int elu_in) {
    __shared__ float Xs[32][129];
    __shared__ float Ws[64][64];
    const float* src = (in == nullptr) ? g_X : in;
    int t = threadIdx.x;
    int n0 = blockIdx.x * 32;

    for (int idx = t; idx < 64 * 64; idx += 256)
        Ws[idx >> 6][idx & 63] = W[idx];

    #pragma unroll
    for (int p = 0; p < 4; p++) {
        int idx4 = p * 256 + t;
        int row = idx4 >> 5;
        int c4  = (idx4 & 31) * 4;
        float4 v = *(const float4*)(src + (size_t)(n0 + row) * DC + c4);
        if (elu_in) { v.x = eluf(v.x); v.y = eluf(v.y); v.z = eluf(v.z); v.w = eluf(v.w); }
        Xs[row][c4 + 0] = v.x; Xs[row][c4 + 1] = v.y;
        Xs[row][c4 + 2] = v.z; Xs[row][c4 + 3] = v.w;
    }
    __syncthreads();

    int r  = t & 31;    // lane -> row (coalesced transposed store)
    int cg = t >> 5;    // warp -> column group
    uint32_t* Pt = (uint32_t*)g_Pt;
    #pragma unroll
    for (int k = 0; k < 16; k++) {
        int c = cg + 8 * k;              // 0..127
        int base = (c >> 6) << 6;        // half select: 0 or 64
        int cl = c & 63;
        float acc = 0.f;
        #pragma unroll
        for (int h = 0; h < 64; h++)
            acc += Xs[r][base + h] * Ws[h][cl];
        Pt[(size_t)c * NN + n0 + r] = tf32r(acc);
    }
}

// ---------------- big GEMM: g_X = elu(SCOMP*(adj @ P) + bias) ----------------
// BM=64, 4-stage cp.async pipeline, 2 CTAs/SM. 256 thr, warp grid 2(M) x 4(N),
// warp tile 32x32, mma.sync m16n8k8 tf32 via ldmatrix-b16 trick.
__global__ __launch_bounds__(256, 2) void gemm_kernel(const float* __restrict__ adj,
                                                      const float* __restrict__ bias) {
    extern __shared__ char smraw[];
    __shared__ float biass[64];
    uint32_t sraw = s2u(smraw);
    uint32_t sb = (sraw + 1023u) & ~1023u;   // 1024-aligned absolute smem base

    const int tid = threadIdx.x, lane = tid & 31, wid = tid >> 5;
    const int mrow = wid >> 2;      // 0..1  -> M offset 0/32
    const int ncol = wid & 3;       // 0..3  -> N offset 0/32/64/96
    const int m0 = blockIdx.x * BM;

    if (tid < 64) biass[tid] = bias[tid];

    // ---- cp.async geometry: 8 thr x 16B cover one 128B row; 32 rows/pass
    const int rr  = tid >> 3;       // 0..31
    const int seg = tid & 7;        // 0..7
    const uint32_t stsOff = (uint32_t)((seg ^ (rr & 7)) * 16);   // swizzled byte col
    const float* __restrict__ Bt = g_Pt;

    auto ISSUE = [&](int i) {   // stage for K-tile i
        uint32_t sA = sb + (uint32_t)(i & (NSTAGE - 1)) * STAGEB;
        uint32_t sB = sA + TILEA;
        int k0 = i * BK;
        #pragma unroll
        for (int p = 0; p < 2; p++) {   // A: 64 rows
            int row = rr + 32 * p;
            cpa16(sA + (uint32_t)row * 128 + stsOff,
                  adj + (size_t)(m0 + row) * NN + k0 + seg * 4);
        }
        #pragma unroll
        for (int p = 0; p < 4; p++) {   // B: 128 rows (all N)
            int row = rr + 32 * p;
            cpa16(sB + (uint32_t)row * 128 + stsOff,
                  Bt + (size_t)row * NN + k0 + seg * 4);
        }
    };

    // ---- ldmatrix lane geometry (32-bit data as b16 pairs) ----
    const int rowL = (lane & 7) | (((lane >> 3) & 1) << 3);  // 0..15
    const int hL   = lane >> 4;                              // 0..1
    uint32_t cp_[4];
    #pragma unroll
    for (int kt = 0; kt < 4; kt++)
        cp_[kt] = (uint32_t)((kt * 32 + hL * 16) ^ ((lane & 7) << 4));
    const uint32_t aBase = (uint32_t)(mrow * 32 + rowL) * 128;
    const uint32_t bBase = (uint32_t)(ncol * 32 + rowL) * 128;

    float d[2][4][4];
    #pragma unroll
    for (int i = 0; i < 2; i++)
        #pragma unroll
        for (int j = 0; j < 4; j++)
            #pragma unroll
            for (int k = 0; k < 4; k++) d[i][j][k] = 0.f;

    // ---- prologue: fill NSTAGE-1 stages ----
    #pragma unroll
    for (int s = 0; s < NSTAGE - 1; s++) {
        ISSUE(s);
        asm volatile("cp.async.commit_group;" ::: "memory");
    }

    #pragma unroll 1
    for (int i = 0; i < KITERS; i++) {
        asm volatile("cp.async.wait_group %0;" :: "n"(NSTAGE - 2) : "memory");
        __syncthreads();                       // stage i resident for all warps

        if (i + NSTAGE - 1 < KITERS) ISSUE(i + NSTAGE - 1);
        asm volatile("cp.async.commit_group;" ::: "memory");   // commit even if empty

        const uint32_t st = sb + (uint32_t)(i & (NSTAGE - 1)) * STAGEB;
        const uint32_t a0 = st + aBase;
        const uint32_t b0 = st + TILEA + bBase;
        #pragma unroll
        for (int kt = 0; kt < 4; kt++) {
            uint32_t af[2][4], bq[2][4];
            #pragma unroll
            for (int mt = 0; mt < 2; mt++) ldsm4(af[mt], a0 + mt * 2048 + cp_[kt]);
            #pragma unroll
            for (int nt = 0; nt < 2; nt++) ldsm4(bq[nt], b0 + nt * 2048 + cp_[kt]);
            #pragma unroll
            for (int mt = 0; mt < 2; mt++)
                #pragma unroll
                for (int n8 = 0; n8 < 4; n8++)
                    mma_tf32(d[mt][n8], af[mt], bq[n8 >> 1][n8 & 1], bq[n8 >> 1][(n8 & 1) + 2]);
        }
        __syncthreads();                       // done reading stage i before refill
    }

    // ---- epilogue: truncation compensation, bias, elu ----
    const int r0 = m0 + mrow * 32 + (lane >> 2);
    const int cb = ncol * 32 + (lane & 3) * 2;
    #pragma unroll
    for (int mt = 0; mt < 2; mt++) {
        #pragma unroll
        for (int n8 = 0; n8 < 4; n8++) {
            int row = r0 + mt * 16;
            int col = cb + n8 * 8;
            float bv0 = biass[col & 63], bv1 = biass[(col + 1) & 63];
            float2 v0 = make_float2(eluf(fmaf(d[mt][n8][0], SCOMP, bv0)),
                                    eluf(fmaf(d[mt][n8][1], SCOMP, bv1)));
            float2 v1 = make_float2(eluf(fmaf(d[mt][n8][2], SCOMP, bv0)),
                                    eluf(fmaf(d[mt][n8][3], SCOMP, bv1)));
            *(float2*)(g_X + (size_t)row * DC + col) = v0;
            *(float2*)(g_X + (size_t)(row + 8) * DC + col) = v1;
        }
    }
}

// ---------------- output: out = X2 @ Wl^T + bl ----------------
__global__ __launch_bounds__(256) void out_kernel(const float* __restrict__ Wl,
                                                  const float* __restrict__ bl,
                                                  float* __restrict__ out) {
    __shared__ float Xs[32][129];
    __shared__ float Wls[32][129];
    int t = threadIdx.x;
    int n0 = blockIdx.x * 32;

    for (int idx = t; idx < 32 * 128; idx += 256)
        Wls[idx >> 7][idx & 127] = Wl[idx];
    #pragma unroll
    for (int p = 0; p < 4; p++) {
        int idx4 = p * 256 + t;
        int row = idx4 >> 5;
        int c4  = (idx4 & 31) * 4;
        float4 v = *(const float4*)(g_X + (size_t)(n0 + row) * DC + c4);
        Xs[row][c4 + 0] = v.x; Xs[row][c4 + 1] = v.y;
        Xs[row][c4 + 2] = v.z; Xs[row][c4 + 3] = v.w;
    }
    __syncthreads();

    int o = t & 31;
    int wb = t >> 5;
    #pragma unroll
    for (int p = 0; p < 4; p++) {
        int r = wb * 4 + p;
        float acc = __ldg(bl + o);
        #pragma unroll
        for (int c = 0; c < 128; c++)
            acc += Xs[r][c] * Wls[o][c];
        out[(size_t)(n0 + r) * 32 + o] = acc;
    }
}

// ---------------- launcher ----------------
extern "C" void kernel_launch(void* const* d_in, const int* in_sizes, int n_in,
                              void* d_out, int out_size) {
    const float* z   = (const float*)d_in[0];
    const float* adj = (const float*)d_in[1];
    const float* W0  = (const float*)d_in[2];
    const float* b0  = (const float*)d_in[3];
    const float* W1  = (const float*)d_in[4];
    const float* b1  = (const float*)d_in[5];
    const float* Wl  = (const float*)d_in[6];
    const float* bl  = (const float*)d_in[7];
    float* out = (float*)d_out;

    cudaFuncSetAttribute(gemm_kernel, cudaFuncAttributeMaxDynamicSharedMemorySize, SMEM_BYTES);

    prep_kernel<<<NN / 32, 256>>>(z, W0, 1);                 // P0^T = (elu(z) @ diag(W0,W0))^T
    gemm_kernel<<<NN / BM, 256, SMEM_BYTES>>>(adj, b0);      // X1 = elu(adj @ P0 + b0)
    prep_kernel<<<NN / 32, 256>>>(nullptr, W1, 0);           // P1^T = (X1 @ diag(W1,W1))^T
    gemm_kernel<<<NN / BM, 256, SMEM_BYTES>>>(adj, b1);      // X2 = elu(adj @ P1 + b1)
    out_kernel<<<NN / 32, 256>>>(Wl, bl, out);               // out = X2 @ Wl^T + bl
}

// round 10
// speedup vs baseline: 1.5087x; 1.5087x over previous
#include <cuda_runtime.h>
#include <cuda_fp16.h>
#include <stdint.h>
#include <math.h>

#define NN 16384
#define DC 128              // concatenated feature cols (= GEMM N)
#define BM 128              // M tile per CTA
#define BK 64               // K tile (64 fp16 = 128 bytes/row in smem)
#define KITERS (NN / BK)    // 256
#define TILEA (BM * 128)    // 16 KB fp16
#define TILEBB (DC * 128)   // 16 KB fp16
#define NSTAGE 4
#define STAGEB (TILEA + TILEBB)               // 32 KB
#define SMEM_BYTES (1024 + NSTAGE * STAGEB)   // ~129 KB, 1 CTA/SM

// ---------------- scratch (device globals; no allocation) ----------------
__device__ __half g_Pt[(size_t)DC * NN];   // B^T: [c][k] n-major fp16 (4 MB, L2-resident)
__device__ float  g_X [(size_t)NN * DC];   // layer activations fp32 (8 MB)

// ---------------- helpers ----------------
__device__ __forceinline__ uint32_t s2u(const void* p) {
    uint32_t a;
    asm("{ .reg .u64 t; cvta.to.shared.u64 t, %1; cvt.u32.u64 %0, t; }" : "=r"(a) : "l"(p));
    return a;
}
__device__ __forceinline__ float eluf(float x) { return x > 0.f ? x : expm1f(x); }
__device__ __forceinline__ void cpa16(uint32_t saddr, const void* gaddr) {
    asm volatile("cp.async.cg.shared.global [%0], [%1], 16;" :: "r"(saddr), "l"(gaddr));
}
__device__ __forceinline__ void ldsm4(uint32_t r[4], uint32_t addr) {
    asm volatile("ldmatrix.sync.aligned.m8n8.x4.shared.b16 {%0,%1,%2,%3}, [%4];"
                 : "=r"(r[0]), "=r"(r[1]), "=r"(r[2]), "=r"(r[3]) : "r"(addr));
}
__device__ __forceinline__ void mma_f16(float d[4], const uint32_t a[4],
                                        uint32_t b0, uint32_t b1) {
    asm volatile("mma.sync.aligned.m16n8k16.row.col.f32.f16.f16.f32 "
                 "{%0,%1,%2,%3}, {%4,%5,%6,%7}, {%8,%9}, {%0,%1,%2,%3};"
                 : "+f"(d[0]), "+f"(d[1]), "+f"(d[2]), "+f"(d[3])
                 : "r"(a[0]), "r"(a[1]), "r"(a[2]), "r"(a[3]), "r"(b0), "r"(b1));
}
__device__ __forceinline__ uint32_t h2u(__half2 h) {
    return *reinterpret_cast<uint32_t*>(&h);
}

// ---------------- prep: P^T[c][k] = fp16( (elu?)in @ blockdiag(W,W) )^T ----------------
__global__ __launch_bounds__(256) void prep_kernel(const float* __restrict__ in,
                                                   const float* __restrict__ W,
                                                   int elu_in) {
    __shared__ float Xs[32][129];
    __shared__ float Ws[64][64];
    const float* src = (in == nullptr) ? g_X : in;
    int t = threadIdx.x;
    int n0 = blockIdx.x * 32;

    for (int idx = t; idx < 64 * 64; idx += 256)
        Ws[idx >> 6][idx & 63] = W[idx];

    #pragma unroll
    for (int p = 0; p < 4; p++) {
        int idx4 = p * 256 + t;
        int row = idx4 >> 5;
        int c4  = (idx4 & 31) * 4;
        float4 v = *(const float4*)(src + (size_t)(n0 + row) * DC + c4);
        if (elu_in) { v.x = eluf(v.x); v.y = eluf(v.y); v.z = eluf(v.z); v.w = eluf(v.w); }
        Xs[row][c4 + 0] = v.x; Xs[row][c4 + 1] = v.y;
        Xs[row][c4 + 2] = v.z; Xs[row][c4 + 3] = v.w;
    }
    __syncthreads();

    int r  = t & 31;    // lane -> row (coalesced transposed store)
    int cg = t >> 5;    // warp -> column group
    #pragma unroll
    for (int k = 0; k < 16; k++) {
        int c = cg + 8 * k;              // 0..127
        int base = (c >> 6) << 6;        // half select: 0 or 64
        int cl = c & 63;
        float acc = 0.f;
        #pragma unroll
        for (int h = 0; h < 64; h++)
            acc += Xs[r][base + h] * Ws[h][cl];
        g_Pt[(size_t)c * NN + n0 + r] = __float2half_rn(acc);
    }
}

// ---------------- big GEMM: g_X = elu(adj @ P + bias), fp16 HMMA ----------------
// A: fp32 gmem -> regs -> fp16 smem (distance-2 prefetch).  B: 4-stage cp.async fp16.
// 256 thr, warp grid 2(M) x 4(N), warp tile 64x32, mma m16n8k16 f16 / f32 accum.
__global__ __launch_bounds__(256, 1) void gemm_kernel(const float* __restrict__ adj,
                                                      const float* __restrict__ bias) {
    extern __shared__ char smraw[];
    __shared__ float biass[64];
    uint32_t sraw = s2u(smraw);
    uint32_t sb = (sraw + 1023u) & ~1023u;   // 1024-aligned absolute smem base
    char* smc = smraw + (sb - sraw);

    const int tid = threadIdx.x, lane = tid & 31, wid = tid >> 5;
    const int mrow = wid >> 2;      // 0..1  -> M offset 0/64
    const int ncol = wid & 3;       // 0..3  -> N offset 0/32/64/96
    const int m0 = blockIdx.x * BM;

    if (tid < 64) biass[tid] = bias[tid];

    // ---- producer geometry: 8 lanes x 16B cover 128B contiguous per row ----
    const int r_a = tid >> 3;       // 0..31 (rows r_a + 32p)
    const int sg  = tid & 7;        // 0..7

    // A: fp32 LDG into registers (2 float4 per row, 4 rows)
    float4 av[4][2];
    auto LDGA = [&](int i) {
        int k0 = i * BK;
        #pragma unroll
        for (int p = 0; p < 4; p++) {
            const float* base = adj + (size_t)(m0 + r_a + 32 * p) * NN + k0 + sg * 4;
            av[p][0] = *(const float4*)(base);
            av[p][1] = *(const float4*)(base + 32);
        }
    };
    // A: convert + swizzled STS.64 into fp16 tile of stage (i&3)
    auto STSA = [&](int i) {
        char* sA = smc + (uint32_t)(i & (NSTAGE - 1)) * STAGEB;
        #pragma unroll
        for (int p = 0; p < 4; p++) {
            int row = r_a + 32 * p;
            #pragma unroll
            for (int q = 0; q < 2; q++) {
                uint2 v;
                v.x = h2u(__floats2half2_rn(av[p][q].x, av[p][q].y));
                v.y = h2u(__floats2half2_rn(av[p][q].z, av[p][q].w));
                uint32_t off = (uint32_t)row * 128 + q * 64 + sg * 8;
                *(uint2*)(sA + (off ^ ((row & 7) << 4))) = v;
            }
        }
    };
    // B: cp.async fp16 (16 KB tile)
    const uint32_t stsOffB = (uint32_t)((sg ^ (r_a & 7)) * 16);
    auto ISSUEB = [&](int i) {
        uint32_t sB = sb + (uint32_t)(i & (NSTAGE - 1)) * STAGEB + TILEA;
        int k0 = i * BK;
        #pragma unroll
        for (int p = 0; p < 4; p++) {
            int row = r_a + 32 * p;
            cpa16(sB + (uint32_t)row * 128 + stsOffB,
                  g_Pt + (size_t)row * NN + k0 + sg * 8);
        }
    };

    // ---- ldmatrix lane geometry (native b16) ----
    const int rowL = lane & 15;
    const int hL   = lane >> 4;
    uint32_t cp_[4];
    #pragma unroll
    for (int kt = 0; kt < 4; kt++)   // kt covers 32B = k16
        cp_[kt] = (uint32_t)((kt * 32 + hL * 16) ^ ((lane & 7) << 4));
    const uint32_t aBase = (uint32_t)(mrow * 64 + rowL) * 128;
    const uint32_t bBase = (uint32_t)(ncol * 32 + rowL) * 128;

    float d[4][4][4];
    #pragma unroll
    for (int i = 0; i < 4; i++)
        #pragma unroll
        for (int j = 0; j < 4; j++)
            #pragma unroll
            for (int k = 0; k < 4; k++) d[i][j][k] = 0.f;

    // ---- prologue ----
    LDGA(0);
    #pragma unroll
    for (int s = 0; s < NSTAGE - 1; s++) {
        ISSUEB(s);
        asm volatile("cp.async.commit_group;" ::: "memory");
    }
    STSA(0);
    LDGA(1);

    #pragma unroll 1
    for (int i = 0; i < KITERS; i++) {
        asm volatile("cp.async.wait_group %0;" :: "n"(NSTAGE - 2) : "memory");
        __syncthreads();                       // stage i fully resident

        if (i + 1 < KITERS) STSA(i + 1);       // regs from LDGA(i+1) at iter i-1
        if (i + 2 < KITERS) LDGA(i + 2);
        if (i + 3 < KITERS) ISSUEB(i + 3);
        asm volatile("cp.async.commit_group;" ::: "memory");

        const uint32_t st = sb + (uint32_t)(i & (NSTAGE - 1)) * STAGEB;
        const uint32_t a0 = st + aBase;
        const uint32_t b0 = st + TILEA + bBase;
        #pragma unroll
        for (int kt = 0; kt < 4; kt++) {       // 4 x k16 = BK 64
            uint32_t af[4][4], bq[2][4];
            #pragma unroll
            for (int mt = 0; mt < 4; mt++) ldsm4(af[mt], a0 + mt * 2048 + cp_[kt]);
            #pragma unroll
            for (int nt = 0; nt < 2; nt++) ldsm4(bq[nt], b0 + nt * 2048 + cp_[kt]);
            #pragma unroll
            for (int mt = 0; mt < 4; mt++)
                #pragma unroll
                for (int n8 = 0; n8 < 4; n8++)
                    mma_f16(d[mt][n8], af[mt], bq[n8 >> 1][n8 & 1], bq[n8 >> 1][(n8 & 1) + 2]);
        }
        __syncthreads();                       // stage i consumed before refill
    }

    // ---- epilogue: bias + elu, float2 stores ----
    const int r0 = m0 + mrow * 64 + (lane >> 2);
    const int cb = ncol * 32 + (lane & 3) * 2;
    #pragma unroll
    for (int mt = 0; mt < 4; mt++) {
        #pragma unroll
        for (int n8 = 0; n8 < 4; n8++) {
            int row = r0 + mt * 16;
            int col = cb + n8 * 8;
            float bv0 = biass[col & 63], bv1 = biass[(col + 1) & 63];
            float2 v0 = make_float2(eluf(d[mt][n8][0] + bv0), eluf(d[mt][n8][1] + bv1));
            float2 v1 = make_float2(eluf(d[mt][n8][2] + bv0), eluf(d[mt][n8][3] + bv1));
            *(float2*)(g_X + (size_t)row * DC + col) = v0;
            *(float2*)(g_X + (size_t)(row + 8) * DC + col) = v1;
        }
    }
}

// ---------------- output: out = X2 @ Wl^T + bl ----------------
__global__ __launch_bounds__(256) void out_kernel(const float* __restrict__ Wl,
                                                  const float* __restrict__ bl,
                                                  float* __restrict__ out) {
    __shared__ float Xs[32][129];
    __shared__ float Wls[32][129];
    int t = threadIdx.x;
    int n0 = blockIdx.x * 32;

    for (int idx = t; idx < 32 * 128; idx += 256)
        Wls[idx >> 7][idx & 127] = Wl[idx];
    #pragma unroll
    for (int p = 0; p < 4; p++) {
        int idx4 = p * 256 + t;
        int row = idx4 >> 5;
        int c4  = (idx4 & 31) * 4;
        float4 v = *(const float4*)(g_X + (size_t)(n0 + row) * DC + c4);
        Xs[row][c4 + 0] = v.x; Xs[row][c4 + 1] = v.y;
        Xs[row][c4 + 2] = v.z; Xs[row][c4 + 3] = v.w;
    }
    __syncthreads();

    int o = t & 31;
    int wb = t >> 5;
    #pragma unroll
    for (int p = 0; p < 4; p++) {
        int r = wb * 4 + p;
        float acc = __ldg(bl + o);
        #pragma unroll
        for (int c = 0; c < 128; c++)
            acc += Xs[r][c] * Wls[o][c];
        out[(size_t)(n0 + r) * 32 + o] = acc;
    }
}

// ---------------- launcher ----------------
extern "C" void kernel_launch(void* const* d_in, const int* in_sizes, int n_in,
                              void* d_out, int out_size) {
    const float* z   = (const float*)d_in[0];
    const float* adj = (const float*)d_in[1];
    const float* W0  = (const float*)d_in[2];
    const float* b0  = (const float*)d_in[3];
    const float* W1  = (const float*)d_in[4];
    const float* b1  = (const float*)d_in[5];
    const float* Wl  = (const float*)d_in[6];
    const float* bl  = (const float*)d_in[7];
    float* out = (float*)d_out;

    cudaFuncSetAttribute(gemm_kernel, cudaFuncAttributeMaxDynamicSharedMemorySize, SMEM_BYTES);

    prep_kernel<<<NN / 32, 256>>>(z, W0, 1);                  // P0^T fp16
    gemm_kernel<<<NN / BM, 256, SMEM_BYTES>>>(adj, b0);       // X1 = elu(adj @ P0 + b0)
    prep_kernel<<<NN / 32, 256>>>(nullptr, W1, 0);            // P1^T fp16
    gemm_kernel<<<NN / BM, 256, SMEM_BYTES>>>(adj, b1);       // X2 = elu(adj @ P1 + b1)
    out_kernel<<<NN / 32, 256>>>(Wl, bl, out);                // out = X2 @ Wl^T + bl
}

// round 13
// speedup vs baseline: 1.5189x; 1.0068x over previous
#include <cuda_runtime.h>
#include <cuda_fp16.h>
#include <stdint.h>
#include <math.h>

#define NN 16384
#define DC 128              // concatenated feature cols (= GEMM N)
#define BM 128              // M tile per CTA
#define BK 64               // K tile (64 fp16 = 128 bytes/row in smem)
#define KITERS (NN / BK)    // 256
#define TILEA (BM * 128)    // 16 KB fp16
#define TILEBB (DC * 128)   // 16 KB fp16
#define NSTAGE 4
#define STAGEB (TILEA + TILEBB)               // 32 KB
#define SMEM_BYTES (1024 + NSTAGE * STAGEB)   // ~129 KB, 1 CTA/SM

// ---------------- scratch (device globals; no allocation) ----------------
__device__ __half g_Pt[(size_t)DC * NN];   // B^T: [c][k] n-major fp16 (4 MB, L2-resident)
__device__ float  g_X [(size_t)NN * DC];   // layer activations fp32 (8 MB)

// ---------------- helpers ----------------
__device__ __forceinline__ uint32_t s2u(const void* p) {
    uint32_t a;
    asm("{ .reg .u64 t; cvta.to.shared.u64 t, %1; cvt.u32.u64 %0, t; }" : "=r"(a) : "l"(p));
    return a;
}
__device__ __forceinline__ float eluf(float x) { return x > 0.f ? x : expm1f(x); }
__device__ __forceinline__ void cpa16(uint32_t saddr, const void* gaddr) {
    asm volatile("cp.async.cg.shared.global [%0], [%1], 16;" :: "r"(saddr), "l"(gaddr));
}
__device__ __forceinline__ void ldsm4(uint32_t r[4], uint32_t addr) {
    asm volatile("ldmatrix.sync.aligned.m8n8.x4.shared.b16 {%0,%1,%2,%3}, [%4];"
                 : "=r"(r[0]), "=r"(r[1]), "=r"(r[2]), "=r"(r[3]) : "r"(addr));
}
__device__ __forceinline__ void mma_f16(float d[4], const uint32_t a[4],
                                        uint32_t b0, uint32_t b1) {
    asm volatile("mma.sync.aligned.m16n8k16.row.col.f32.f16.f16.f32 "
                 "{%0,%1,%2,%3}, {%4,%5,%6,%7}, {%8,%9}, {%0,%1,%2,%3};"
                 : "+f"(d[0]), "+f"(d[1]), "+f"(d[2]), "+f"(d[3])
                 : "r"(a[0]), "r"(a[1]), "r"(a[2]), "r"(a[3]), "r"(b0), "r"(b1));
}
__device__ __forceinline__ uint32_t h2u(__half2 h) {
    return *reinterpret_cast<uint32_t*>(&h);
}

// ---------------- prep: P^T[c][k] = fp16( (elu?)in @ blockdiag(W,W) )^T ----------------
__global__ __launch_bounds__(256) void prep_kernel(const float* __restrict__ in,
                                                   const float* __restrict__ W,
                                                   int elu_in) {
    __shared__ float Xs[32][129];
    __shared__ float Ws[64][64];
    const float* src = (in == nullptr) ? g_X : in;
    int t = threadIdx.x;
    int n0 = blockIdx.x * 32;

    for (int idx = t; idx < 64 * 64; idx += 256)
        Ws[idx >> 6][idx & 63] = W[idx];

    #pragma unroll
    for (int p = 0; p < 4; p++) {
        int idx4 = p * 256 + t;
        int row = idx4 >> 5;
        int c4  = (idx4 & 31) * 4;
        float4 v = *(const float4*)(src + (size_t)(n0 + row) * DC + c4);
        if (elu_in) { v.x = eluf(v.x); v.y = eluf(v.y); v.z = eluf(v.z); v.w = eluf(v.w); }
        Xs[row][c4 + 0] = v.x; Xs[row][c4 + 1] = v.y;
        Xs[row][c4 + 2] = v.z; Xs[row][c4 + 3] = v.w;
    }
    __syncthreads();

    int r  = t & 31;    // lane -> row (coalesced transposed store)
    int cg = t >> 5;    // warp -> column group
    #pragma unroll
    for (int k = 0; k < 16; k++) {
        int c = cg + 8 * k;              // 0..127
        int base = (c >> 6) << 6;        // half select: 0 or 64
        int cl = c & 63;
        float acc = 0.f;
        #pragma unroll
        for (int h = 0; h < 64; h++)
            acc += Xs[r][base + h] * Ws[h][cl];
        g_Pt[(size_t)c * NN + n0 + r] = __float2half_rn(acc);
    }
}

// ---------------- big GEMM: g_X = elu(adj @ P + bias), fp16 HMMA ----------------
// A: fp32 gmem -> regs -> fp16 smem (distance-2 prefetch).  B: 4-stage cp.async fp16.
// Single barrier per iter; fragment double-buffer pipelines LDSM against HMMA.
__global__ __launch_bounds__(256, 1) void gemm_kernel(const float* __restrict__ adj,
                                                      const float* __restrict__ bias) {
    extern __shared__ char smraw[];
    __shared__ float biass[64];
    uint32_t sraw = s2u(smraw);
    uint32_t sb = (sraw + 1023u) & ~1023u;   // 1024-aligned absolute smem base
    char* smc = smraw + (sb - sraw);

    const int tid = threadIdx.x, lane = tid & 31, wid = tid >> 5;
    const int mrow = wid >> 2;      // 0..1  -> M offset 0/64
    const int ncol = wid & 3;       // 0..3  -> N offset 0/32/64/96
    const int m0 = blockIdx.x * BM;

    if (tid < 64) biass[tid] = bias[tid];

    // ---- producer geometry: 8 lanes x 16B cover 128B contiguous per row ----
    const int r_a = tid >> 3;       // 0..31 (rows r_a + 32p)
    const int sg  = tid & 7;        // 0..7

    // A: fp32 LDG into registers (2 float4 per row, 4 rows)
    float4 av[4][2];
    auto LDGA = [&](int i) {
        int k0 = i * BK;
        #pragma unroll
        for (int p = 0; p < 4; p++) {
            const float* base = adj + (size_t)(m0 + r_a + 32 * p) * NN + k0 + sg * 4;
            av[p][0] = *(const float4*)(base);
            av[p][1] = *(const float4*)(base + 32);
        }
    };
    // A: convert + swizzled STS.64 into fp16 tile of stage (i&3)
    auto STSA = [&](int i) {
        char* sA = smc + (uint32_t)(i & (NSTAGE - 1)) * STAGEB;
        #pragma unroll
        for (int p = 0; p < 4; p++) {
            int row = r_a + 32 * p;
            #pragma unroll
            for (int q = 0; q < 2; q++) {
                uint2 v;
                v.x = h2u(__floats2half2_rn(av[p][q].x, av[p][q].y));
                v.y = h2u(__floats2half2_rn(av[p][q].z, av[p][q].w));
                uint32_t off = (uint32_t)row * 128 + q * 64 + sg * 8;
                *(uint2*)(sA + (off ^ ((row & 7) << 4))) = v;
            }
        }
    };
    // B: cp.async fp16 (16 KB tile)
    const uint32_t stsOffB = (uint32_t)((sg ^ (r_a & 7)) * 16);
    auto ISSUEB = [&](int i) {
        uint32_t sB = sb + (uint32_t)(i & (NSTAGE - 1)) * STAGEB + TILEA;
        int k0 = i * BK;
        #pragma unroll
        for (int p = 0; p < 4; p++) {
            int row = r_a + 32 * p;
            cpa16(sB + (uint32_t)row * 128 + stsOffB,
                  g_Pt + (size_t)row * NN + k0 + sg * 8);
        }
    };

    // ---- ldmatrix lane geometry (native b16) ----
    const int rowL = lane & 15;
    const int hL   = lane >> 4;
    uint32_t cp_[4];
    #pragma unroll
    for (int kt = 0; kt < 4; kt++)   // kt covers 32B = k16
        cp_[kt] = (uint32_t)((kt * 32 + hL * 16) ^ ((lane & 7) << 4));
    const uint32_t aBase = (uint32_t)(mrow * 64 + rowL) * 128;
    const uint32_t bBase = (uint32_t)(ncol * 32 + rowL) * 128;

    float d[4][4][4];
    #pragma unroll
    for (int i = 0; i < 4; i++)
        #pragma unroll
        for (int j = 0; j < 4; j++)
            #pragma unroll
            for (int k = 0; k < 4; k++) d[i][j][k] = 0.f;

    // fragment double buffer
    uint32_t af[2][4][4], bq[2][2][4];

    // ---- prologue ----
    LDGA(0);
    #pragma unroll
    for (int s = 0; s < NSTAGE - 1; s++) {
        ISSUEB(s);
        asm volatile("cp.async.commit_group;" ::: "memory");
    }
    STSA(0);
    LDGA(1);

    #pragma unroll 1
    for (int i = 0; i < KITERS; i++) {
        asm volatile("cp.async.wait_group %0;" :: "n"(NSTAGE - 2) : "memory");
        __syncthreads();   // single barrier per iter: stage i resident & visible.
        // Safety: STSA below targets buf (i+1)%4 (read only after next barrier);
        // ISSUEB targets buf (i+3)%4 == (i-1)%4 (reads finished before this barrier).

        if (i + 1 < KITERS) STSA(i + 1);       // regs from LDGA(i+1) at iter i-1
        if (i + 2 < KITERS) LDGA(i + 2);
        if (i + 3 < KITERS) ISSUEB(i + 3);
        asm volatile("cp.async.commit_group;" ::: "memory");

        const uint32_t st = sb + (uint32_t)(i & (NSTAGE - 1)) * STAGEB;
        const uint32_t a0 = st + aBase;
        const uint32_t b0 = st + TILEA + bBase;

        // prefetch fragments for kt=0
        #pragma unroll
        for (int mt = 0; mt < 4; mt++) ldsm4(af[0][mt], a0 + mt * 2048 + cp_[0]);
        #pragma unroll
        for (int nt = 0; nt < 2; nt++) ldsm4(bq[0][nt], b0 + nt * 2048 + cp_[0]);

        #pragma unroll
        for (int kt = 0; kt < 4; kt++) {       // 4 x k16 = BK 64
            const int cur = kt & 1, nxt = cur ^ 1;
            if (kt < 3) {                      // overlap LDSM(kt+1) with HMMA(kt)
                #pragma unroll
                for (int mt = 0; mt < 4; mt++) ldsm4(af[nxt][mt], a0 + mt * 2048 + cp_[kt + 1]);
                #pragma unroll
                for (int nt = 0; nt < 2; nt++) ldsm4(bq[nxt][nt], b0 + nt * 2048 + cp_[kt + 1]);
            }
            #pragma unroll
            for (int mt = 0; mt < 4; mt++)
                #pragma unroll
                for (int n8 = 0; n8 < 4; n8++)
                    mma_f16(d[mt][n8], af[cur][mt],
                            bq[cur][n8 >> 1][n8 & 1], bq[cur][n8 >> 1][(n8 & 1) + 2]);
        }
    }

    // ---- epilogue: bias + elu, float2 stores ----
    const int r0 = m0 + mrow * 64 + (lane >> 2);
    const int cb = ncol * 32 + (lane & 3) * 2;
    #pragma unroll
    for (int mt = 0; mt < 4; mt++) {
        #pragma unroll
        for (int n8 = 0; n8 < 4; n8++) {
            int row = r0 + mt * 16;
            int col = cb + n8 * 8;
            float bv0 = biass[col & 63], bv1 = biass[(col + 1) & 63];
            float2 v0 = make_float2(eluf(d[mt][n8][0] + bv0), eluf(d[mt][n8][1] + bv1));
            float2 v1 = make_float2(eluf(d[mt][n8][2] + bv0), eluf(d[mt][n8][3] + bv1));
            *(float2*)(g_X + (size_t)row * DC + col) = v0;
            *(float2*)(g_X + (size_t)(row + 8) * DC + col) = v1;
        }
    }
}

// ---------------- output: out = X2 @ Wl^T + bl ----------------
__global__ __launch_bounds__(256) void out_kernel(const float* __restrict__ Wl,
                                                  const float* __restrict__ bl,
                                                  float* __restrict__ out) {
    __shared__ float Xs[32][129];
    __shared__ float Wls[32][129];
    int t = threadIdx.x;
    int n0 = blockIdx.x * 32;

    for (int idx = t; idx < 32 * 128; idx += 256)
        Wls[idx >> 7][idx & 127] = Wl[idx];
    #pragma unroll
    for (int p = 0; p < 4; p++) {
        int idx4 = p * 256 + t;
        int row = idx4 >> 5;
        int c4  = (idx4 & 31) * 4;
        float4 v = *(const float4*)(g_X + (size_t)(n0 + row) * DC + c4);
        Xs[row][c4 + 0] = v.x; Xs[row][c4 + 1] = v.y;
        Xs[row][c4 + 2] = v.z; Xs[row][c4 + 3] = v.w;
    }
    __syncthreads();

    int o = t & 31;
    int wb = t >> 5;
    #pragma unroll
    for (int p = 0; p < 4; p++) {
        int r = wb * 4 + p;
        float acc = __ldg(bl + o);
        #pragma unroll
        for (int c = 0; c < 128; c++)
            acc += Xs[r][c] * Wls[o][c];
        out[(size_t)(n0 + r) * 32 + o] = acc;
    }
}

// ---------------- launcher ----------------
extern "C" void kernel_launch(void* const* d_in, const int* in_sizes, int n_in,
                              void* d_out, int out_size) {
    const float* z   = (const float*)d_in[0];
    const float* adj = (const float*)d_in[1];
    const float* W0  = (const float*)d_in[2];
    const float* b0  = (const float*)d_in[3];
    const float* W1  = (const float*)d_in[4];
    const float* b1  = (const float*)d_in[5];
    const float* Wl  = (const float*)d_in[6];
    const float* bl  = (const float*)d_in[7];
    float* out = (float*)d_out;

    cudaFuncSetAttribute(gemm_kernel, cudaFuncAttributeMaxDynamicSharedMemorySize, SMEM_BYTES);

    prep_kernel<<<NN / 32, 256>>>(z, W0, 1);                  // P0^T fp16
    gemm_kernel<<<NN / BM, 256, SMEM_BYTES>>>(adj, b0);       // X1 = elu(adj @ P0 + b0)
    prep_kernel<<<NN / 32, 256>>>(nullptr, W1, 0);            // P1^T fp16
    gemm_kernel<<<NN / BM, 256, SMEM_BYTES>>>(adj, b1);       // X2 = elu(adj @ P1 + b1)
    out_kernel<<<NN / 32, 256>>>(Wl, bl, out);                // out = X2 @ Wl^T + bl
}

// round 14
// speedup vs baseline: 1.5215x; 1.0017x over previous
#include <cuda_runtime.h>
#include <cuda_fp16.h>
#include <stdint.h>
#include <math.h>

#define NN 16384
#define DC 128              // concatenated feature cols (= GEMM N)
#define BM 128              // M tile per CTA
#define BK 64               // K tile (64 fp16 = 128 bytes/row in smem)
#define KITERS (NN / BK)    // 256
#define TILEA (BM * 128)    // 16 KB fp16
#define TILEBB (DC * 128)   // 16 KB fp16
#define NSTAGE 4
#define STAGEB (TILEA + TILEBB)               // 32 KB
#define SMEM_BYTES (1024 + NSTAGE * STAGEB)   // ~129 KB, 1 CTA/SM

// ---------------- scratch (device globals; no allocation) ----------------
__device__ __half g_Pt[(size_t)DC * NN];   // B^T: [c][k] n-major fp16 (4 MB, L2-resident)
__device__ float  g_X [(size_t)NN * DC];   // layer activations fp32 (8 MB)

// ---------------- helpers ----------------
__device__ __forceinline__ uint32_t s2u(const void* p) {
    uint32_t a;
    asm("{ .reg .u64 t; cvta.to.shared.u64 t, %1; cvt.u32.u64 %0, t; }" : "=r"(a) : "l"(p));
    return a;
}
__device__ __forceinline__ float eluf(float x) { return x > 0.f ? x : expm1f(x); }
__device__ __forceinline__ void cpa16(uint32_t saddr, const void* gaddr) {
    asm volatile("cp.async.cg.shared.global [%0], [%1], 16;" :: "r"(saddr), "l"(gaddr));
}
__device__ __forceinline__ void ldsm4(uint32_t r[4], uint32_t addr) {
    asm volatile("ldmatrix.sync.aligned.m8n8.x4.shared.b16 {%0,%1,%2,%3}, [%4];"
                 : "=r"(r[0]), "=r"(r[1]), "=r"(r[2]), "=r"(r[3]) : "r"(addr));
}
__device__ __forceinline__ void mma_f16(float d[4], const uint32_t a[4],
                                        uint32_t b0, uint32_t b1) {
    asm volatile("mma.sync.aligned.m16n8k16.row.col.f32.f16.f16.f32 "
                 "{%0,%1,%2,%3}, {%4,%5,%6,%7}, {%8,%9}, {%0,%1,%2,%3};"
                 : "+f"(d[0]), "+f"(d[1]), "+f"(d[2]), "+f"(d[3])
                 : "r"(a[0]), "r"(a[1]), "r"(a[2]), "r"(a[3]), "r"(b0), "r"(b1));
}
__device__ __forceinline__ uint32_t h2u(__half2 h) {
    return *reinterpret_cast<uint32_t*>(&h);
}

// ---------------- prep: P^T[c][k] = fp16( (elu?)in @ blockdiag(W,W) )^T ----------------
__global__ __launch_bounds__(256) void prep_kernel(const float* __restrict__ in,
                                                   const float* __restrict__ W,
                                                   int elu_in) {
    __shared__ float Xs[32][129];
    __shared__ float Ws[64][64];
    const float* src = (in == nullptr) ? g_X : in;
    int t = threadIdx.x;
    int n0 = blockIdx.x * 32;

    for (int idx = t; idx < 64 * 64; idx += 256)
        Ws[idx >> 6][idx & 63] = W[idx];

    #pragma unroll
    for (int p = 0; p < 4; p++) {
        int idx4 = p * 256 + t;
        int row = idx4 >> 5;
        int c4  = (idx4 & 31) * 4;
        float4 v = *(const float4*)(src + (size_t)(n0 + row) * DC + c4);
        if (elu_in) { v.x = eluf(v.x); v.y = eluf(v.y); v.z = eluf(v.z); v.w = eluf(v.w); }
        Xs[row][c4 + 0] = v.x; Xs[row][c4 + 1] = v.y;
        Xs[row][c4 + 2] = v.z; Xs[row][c4 + 3] = v.w;
    }
    __syncthreads();

    int r  = t & 31;    // lane -> row (coalesced transposed store)
    int cg = t >> 5;    // warp -> column group
    #pragma unroll
    for (int k = 0; k < 16; k++) {
        int c = cg + 8 * k;              // 0..127
        int base = (c >> 6) << 6;        // half select: 0 or 64
        int cl = c & 63;
        float acc = 0.f;
        #pragma unroll
        for (int h = 0; h < 64; h++)
            acc += Xs[r][base + h] * Ws[h][cl];
        g_Pt[(size_t)c * NN + n0 + r] = __float2half_rn(acc);
    }
}

// ---------------- big GEMM: g_X = elu(adj @ P + bias), fp16 HMMA ----------------
// A: fp32 gmem -> regs -> fp16 smem (distance-2 prefetch).  B: 4-stage cp.async fp16.
// Single barrier per iter; fragment double-buffer pipelines LDSM against HMMA.
__global__ __launch_bounds__(256, 1) void gemm_kernel(const float* __restrict__ adj,
                                                      const float* __restrict__ bias) {
    extern __shared__ char smraw[];
    __shared__ float biass[64];
    uint32_t sraw = s2u(smraw);
    uint32_t sb = (sraw + 1023u) & ~1023u;   // 1024-aligned absolute smem base
    char* smc = smraw + (sb - sraw);

    const int tid = threadIdx.x, lane = tid & 31, wid = tid >> 5;
    const int mrow = wid >> 2;      // 0..1  -> M offset 0/64
    const int ncol = wid & 3;       // 0..3  -> N offset 0/32/64/96
    const int m0 = blockIdx.x * BM;

    if (tid < 64) biass[tid] = bias[tid];

    // ---- producer geometry: 8 lanes x 16B cover 128B contiguous per row ----
    const int r_a = tid >> 3;       // 0..31 (rows r_a + 32p)
    const int sg  = tid & 7;        // 0..7

    // A: fp32 LDG into registers (2 float4 per row, 4 rows)
    float4 av[4][2];
    auto LDGA = [&](int i) {
        int k0 = i * BK;
        #pragma unroll
        for (int p = 0; p < 4; p++) {
            const float* base = adj + (size_t)(m0 + r_a + 32 * p) * NN + k0 + sg * 4;
            av[p][0] = *(const float4*)(base);
            av[p][1] = *(const float4*)(base + 32);
        }
    };
    // A: convert + swizzled STS.64 into fp16 tile of stage (i&3)
    auto STSA = [&](int i) {
        char* sA = smc + (uint32_t)(i & (NSTAGE - 1)) * STAGEB;
        #pragma unroll
        for (int p = 0; p < 4; p++) {
            int row = r_a + 32 * p;
            #pragma unroll
            for (int q = 0; q < 2; q++) {
                uint2 v;
                v.x = h2u(__floats2half2_rn(av[p][q].x, av[p][q].y));
                v.y = h2u(__floats2half2_rn(av[p][q].z, av[p][q].w));
                uint32_t off = (uint32_t)row * 128 + q * 64 + sg * 8;
                *(uint2*)(sA + (off ^ ((row & 7) << 4))) = v;
            }
        }
    };
    // B: cp.async fp16 (16 KB tile)
    const uint32_t stsOffB = (uint32_t)((sg ^ (r_a & 7)) * 16);
    auto ISSUEB = [&](int i) {
        uint32_t sB = sb + (uint32_t)(i & (NSTAGE - 1)) * STAGEB + TILEA;
        int k0 = i * BK;
        #pragma unroll
        for (int p = 0; p < 4; p++) {
            int row = r_a + 32 * p;
            cpa16(sB + (uint32_t)row * 128 + stsOffB,
                  g_Pt + (size_t)row * NN + k0 + sg * 8);
        }
    };

    // ---- ldmatrix lane geometry (native b16) ----
    const int rowL = lane & 15;
    const int hL   = lane >> 4;
    uint32_t cp_[4];
    #pragma unroll
    for (int kt = 0; kt < 4; kt++)   // kt covers 32B = k16
        cp_[kt] = (uint32_t)((kt * 32 + hL * 16) ^ ((lane & 7) << 4));
    const uint32_t aBase = (uint32_t)(mrow * 64 + rowL) * 128;
    const uint32_t bBase = (uint32_t)(ncol * 32 + rowL) * 128;

    float d[4][4][4];
    #pragma unroll
    for (int i = 0; i < 4; i++)
        #pragma unroll
        for (int j = 0; j < 4; j++)
            #pragma unroll
            for (int k = 0; k < 4; k++) d[i][j][k] = 0.f;

    // fragment double buffer
    uint32_t af[2][4][4], bq[2][2][4];

    // ---- prologue ----
    LDGA(0);
    #pragma unroll
    for (int s = 0; s < NSTAGE - 1; s++) {
        ISSUEB(s);
        asm volatile("cp.async.commit_group;" ::: "memory");
    }
    STSA(0);
    LDGA(1);

    #pragma unroll 1
    for (int i = 0; i < KITERS; i++) {
        asm volatile("cp.async.wait_group %0;" :: "n"(NSTAGE - 2) : "memory");
        __syncthreads();   // single barrier per iter: stage i resident & visible.
        // Safety: STSA below targets buf (i+1)%4 (read only after next barrier);
        // ISSUEB targets buf (i+3)%4 == (i-1)%4 (reads finished before this barrier).

        if (i + 1 < KITERS) STSA(i + 1);       // regs from LDGA(i+1) at iter i-1
        if (i + 2 < KITERS) LDGA(i + 2);
        if (i + 3 < KITERS) ISSUEB(i + 3);
        asm volatile("cp.async.commit_group;" ::: "memory");

        const uint32_t st = sb + (uint32_t)(i & (NSTAGE - 1)) * STAGEB;
        const uint32_t a0 = st + aBase;
        const uint32_t b0 = st + TILEA + bBase;

        // prefetch fragments for kt=0
        #pragma unroll
        for (int mt = 0; mt < 4; mt++) ldsm4(af[0][mt], a0 + mt * 2048 + cp_[0]);
        #pragma unroll
        for (int nt = 0; nt < 2; nt++) ldsm4(bq[0][nt], b0 + nt * 2048 + cp_[0]);

        #pragma unroll
        for (int kt = 0; kt < 4; kt++) {       // 4 x k16 = BK 64
            const int cur = kt & 1, nxt = cur ^ 1;
            if (kt < 3) {                      // overlap LDSM(kt+1) with HMMA(kt)
                #pragma unroll
                for (int mt = 0; mt < 4; mt++) ldsm4(af[nxt][mt], a0 + mt * 2048 + cp_[kt + 1]);
                #pragma unroll
                for (int nt = 0; nt < 2; nt++) ldsm4(bq[nxt][nt], b0 + nt * 2048 + cp_[kt + 1]);
            }
            #pragma unroll
            for (int mt = 0; mt < 4; mt++)
                #pragma unroll
                for (int n8 = 0; n8 < 4; n8++)
                    mma_f16(d[mt][n8], af[cur][mt],
                            bq[cur][n8 >> 1][n8 & 1], bq[cur][n8 >> 1][(n8 & 1) + 2]);
        }
    }

    // ---- epilogue: bias + elu, float2 stores ----
    const int r0 = m0 + mrow * 64 + (lane >> 2);
    const int cb = ncol * 32 + (lane & 3) * 2;
    #pragma unroll
    for (int mt = 0; mt < 4; mt++) {
        #pragma unroll
        for (int n8 = 0; n8 < 4; n8++) {
            int row = r0 + mt * 16;
            int col = cb + n8 * 8;
            float bv0 = biass[col & 63], bv1 = biass[(col + 1) & 63];
            float2 v0 = make_float2(eluf(d[mt][n8][0] + bv0), eluf(d[mt][n8][1] + bv1));
            float2 v1 = make_float2(eluf(d[mt][n8][2] + bv0), eluf(d[mt][n8][3] + bv1));
            *(float2*)(g_X + (size_t)row * DC + col) = v0;
            *(float2*)(g_X + (size_t)(row + 8) * DC + col) = v1;
        }
    }
}

// ---------------- output: out = X2 @ Wl^T + bl ----------------
__global__ __launch_bounds__(256) void out_kernel(const float* __restrict__ Wl,
                                                  const float* __restrict__ bl,
                                                  float* __restrict__ out) {
    __shared__ float Xs[32][129];
    __shared__ float Wls[32][129];
    int t = threadIdx.x;
    int n0 = blockIdx.x * 32;

    for (int idx = t; idx < 32 * 128; idx += 256)
        Wls[idx >> 7][idx & 127] = Wl[idx];
    #pragma unroll
    for (int p = 0; p < 4; p++) {
        int idx4 = p * 256 + t;
        int row = idx4 >> 5;
        int c4  = (idx4 & 31) * 4;
        float4 v = *(const float4*)(g_X + (size_t)(n0 + row) * DC + c4);
        Xs[row][c4 + 0] = v.x; Xs[row][c4 + 1] = v.y;
        Xs[row][c4 + 2] = v.z; Xs[row][c4 + 3] = v.w;
    }
    __syncthreads();

    int o = t & 31;
    int wb = t >> 5;
    #pragma unroll
    for (int p = 0; p < 4; p++) {
        int r = wb * 4 + p;
        float acc = __ldg(bl + o);
        #pragma unroll
        for (int c = 0; c < 128; c++)
            acc += Xs[r][c] * Wls[o][c];
        out[(size_t)(n0 + r) * 32 + o] = acc;
    }
}

// ---------------- launcher ----------------
extern "C" void kernel_launch(void* const* d_in, const int* in_sizes, int n_in,
                              void* d_out, int out_size) {
    const float* z   = (const float*)d_in[0];
    const float* adj = (const float*)d_in[1];
    const float* W0  = (const float*)d_in[2];
    const float* b0  = (const float*)d_in[3];
    const float* W1  = (const float*)d_in[4];
    const float* b1  = (const float*)d_in[5];
    const float* Wl  = (const float*)d_in[6];
    const float* bl  = (const float*)d_in[7];
    float* out = (float*)d_out;

    cudaFuncSetAttribute(gemm_kernel, cudaFuncAttributeMaxDynamicSharedMemorySize, SMEM_BYTES);

    prep_kernel<<<NN / 32, 256>>>(z, W0, 1);                  // P0^T fp16
    gemm_kernel<<<NN / BM, 256, SMEM_BYTES>>>(adj, b0);       // X1 = elu(adj @ P0 + b0)
    prep_kernel<<<NN / 32, 256>>>(nullptr, W1, 0);            // P1^T fp16
    gemm_kernel<<<NN / BM, 256, SMEM_BYTES>>>(adj, b1);       // X2 = elu(adj @ P1 + b1)
    out_kernel<<<NN / 32, 256>>>(Wl, bl, out);                // out = X2 @ Wl^T + bl
}